// round 11
// baseline (speedup 1.0000x reference)
#include <cuda_runtime.h>
#include <cuda_bf16.h>
#include <math.h>
#include <string.h>

typedef unsigned long long ull;
typedef unsigned int u32;

// Problem constants
#define BATCH   8
#define SEQ     2048
#define DMODEL  1024
#define DSPACE  64
#define N_QK    512
#define N_V     256
#define N_REL   128
#define N_VAL   32
#define N_TOT   928
#define K_QK    64
#define K_V     32
#define K_REL   16
#define K_VAL   3

#define TPB      128
#define NTHREADS 256
#define NBLOCKS  128               // 16 per batch

// Output layout (float32, reference return order)
#define OFF_IDXQK 0
#define OFF_IDXV  (OFF_IDXQK + BATCH*K_QK)
#define OFF_RWQ   (OFF_IDXV  + BATCH*K_V)
#define OFF_RWK   (OFF_RWQ   + BATCH*N_REL)
#define OFF_VW    (OFF_RWK   + BATCH*N_REL)
#define OFF_WQK   (OFF_VW    + BATCH*N_VAL)
#define OFF_WV    (OFF_WQK   + BATCH*N_QK)

// u32-stride for all MMA smem tiles (32 payload + 4 pad) -> conflict-free frags
#define S36 36

// Shared memory byte offsets
#define SM_A2H   0          // u32[128][36] H hi  (18432)
#define SM_A2L   18432      // u32[128][36] H lo  (18432)
// staging region @36864:
//   GEMM1 buf0: XH 36864(18432) XL 55296(18432) WH 73728(9216) WL 82944(9216)
//   GEMM1 buf1: XH 92160 XL 110592 WH 129024 WL 138240  (end 147456)
//   GEMM2 emb:  EH 36864 (256*36*4=36864)  EL 73728     (end 110592)
//   finalize: sws @0 (aliases A2H), flag @4096
#define SM_EH    36864
#define SM_EL    73728
#define SM_WACC  147456     // float[4][928] = 14848
#define SM_IMP   162304     // float[128]
#define SM_BIAS  162816     // float[64]
#define SM_RS    163072     // float[256]
#define SM_ALPHA 164096     // float[4][128]
#define SM_FLAG  166144
#define SMEM_BYTES 166400

// device scratch (no allocation allowed)
__device__ u32 g_embH[N_TOT * 32];    // bf16 pairs [n][k2], k2 = d/2
__device__ u32 g_embL[N_TOT * 32];
__device__ u32 g_WH[DSPACE * 512];    // bf16 pairs [n=dspace][k2], k2 = k/2
__device__ u32 g_WL[DSPACE * 512];
__device__ float g_wpart[NBLOCKS][N_TOT];
__device__ int   g_cnt[BATCH];

// ---------------- helpers ----------------
// fp32 pair -> bf16x2 hi (return) / lo (out param); low 16 bits = first elem
__device__ __forceinline__ u32 split2(float a, float b, u32& lo) {
    __nv_bfloat162 h = __floats2bfloat162_rn(a, b);
    float ha = __low2float(h), hb = __high2float(h);
    __nv_bfloat162 l = __floats2bfloat162_rn(a - ha, b - hb);
    u32 uh, ul;
    memcpy(&uh, &h, 4);
    memcpy(&ul, &l, 4);
    lo = ul;
    return uh;
}

__device__ __forceinline__ void mma_bf16(float* c, const u32* a, u32 b0, u32 b1) {
    asm volatile(
        "mma.sync.aligned.m16n8k16.row.col.f32.bf16.bf16.f32 "
        "{%0,%1,%2,%3}, {%4,%5,%6,%7}, {%8,%9}, {%0,%1,%2,%3};"
        : "+f"(c[0]), "+f"(c[1]), "+f"(c[2]), "+f"(c[3])
        : "r"(a[0]), "r"(a[1]), "r"(a[2]), "r"(a[3]), "r"(b0), "r"(b1));
}

// ---------------- prep kernels ----------------
__global__ void prep_emb(const float* __restrict__ emb) {
    int r = blockIdx.x;     // neuron
    int t = threadIdx.x;    // dim
    __shared__ float s[64];
    __shared__ float e[64];
    float v = emb[r * DSPACE + t];
    s[t] = v * v;
    __syncthreads();
    #pragma unroll
    for (int o = 32; o > 0; o >>= 1) {
        if (t < o) s[t] += s[t + o];
        __syncthreads();
    }
    e[t] = v / sqrtf(s[0]);
    __syncthreads();
    if (t < 32) {
        u32 lo, hi = split2(e[2 * t], e[2 * t + 1], lo);
        g_embH[r * 32 + t] = hi;
        g_embL[r * 32 + t] = lo;
    }
}

__global__ void prep_w(const float* __restrict__ W) {
    int n = blockIdx.x;     // dspace col
    int tid = threadIdx.x;
    if (n == 0 && tid < BATCH) g_cnt[tid] = 0;
    for (int k2 = tid; k2 < 512; k2 += 256) {
        float a = W[(size_t)(2 * k2) * DSPACE + n];
        float b = W[(size_t)(2 * k2 + 1) * DSPACE + n];
        u32 lo, hi = split2(a, b, lo);
        g_WH[n * 512 + k2] = hi;
        g_WL[n * 512 + k2] = lo;
    }
}

// ---------------- finalize helper ----------------
template<int NN, int KK>
__device__ __forceinline__ void topk_flags(const float* ws, int* flag, int tid) {
    for (int i = tid; i < NN; i += NTHREADS) {
        float wi = ws[i]; int r = 0;
        #pragma unroll 16
        for (int j = 0; j < NN; j++) {
            float wj = ws[j];
            r += (wj > wi) || (wj == wi && j < i);
        }
        flag[i] = (r < KK) ? 1 : 0;
    }
}

// ---------------- GEMM2 tile: c[2][4] += H[32tok] x emb[8n] over K=64 ----------------
__device__ __forceinline__ void g2_tile(const u32* __restrict__ A2H, const u32* __restrict__ A2L,
                                        const u32* __restrict__ EH, const u32* __restrict__ EL,
                                        int tg, int g, int t, int n0loc, float c[2][4]) {
    #pragma unroll
    for (int ks = 0; ks < 4; ks++) {
        int bi = (n0loc + g) * S36 + 8 * ks + t;
        u32 bh0 = EH[bi], bh1 = EH[bi + 4];
        u32 bl0 = EL[bi], bl1 = EL[bi + 4];
        #pragma unroll
        for (int mc = 0; mc < 2; mc++) {
            int r0 = (32 * tg + 16 * mc + g) * S36 + 8 * ks + t;
            u32 ah[4] = {A2H[r0], A2H[r0 + 8 * S36], A2H[r0 + 4], A2H[r0 + 8 * S36 + 4]};
            u32 al[4] = {A2L[r0], A2L[r0 + 8 * S36], A2L[r0 + 4], A2L[r0 + 8 * S36 + 4]};
            mma_bf16(c[mc], ah, bh0, bh1);
            mma_bf16(c[mc], ah, bl0, bl1);
            mma_bf16(c[mc], al, bh0, bh1);
        }
    }
}

// ---------------- main fused kernel ----------------
__global__ void __launch_bounds__(NTHREADS, 1)
main_kernel(const float* __restrict__ x, const float* __restrict__ imp,
            const float* __restrict__ Wm, const float* __restrict__ bias,
            float* __restrict__ out)
{
    extern __shared__ char sm[];
    u32* A2H = (u32*)(sm + SM_A2H);
    u32* A2L = (u32*)(sm + SM_A2L);
    u32* EH  = (u32*)(sm + SM_EH);
    u32* EL  = (u32*)(sm + SM_EL);
    float* wacc   = (float*)(sm + SM_WACC);
    float* impS   = (float*)(sm + SM_IMP);
    float* biasS  = (float*)(sm + SM_BIAS);
    float* rsS    = (float*)(sm + SM_RS);
    float* alphaS = (float*)(sm + SM_ALPHA);

    u32* XHb[2] = {(u32*)(sm + 36864), (u32*)(sm + 92160)};
    u32* XLb[2] = {(u32*)(sm + 55296), (u32*)(sm + 110592)};
    u32* WHb[2] = {(u32*)(sm + 73728), (u32*)(sm + 129024)};
    u32* WLb[2] = {(u32*)(sm + 82944), (u32*)(sm + 138240)};

    const int tid = threadIdx.x;
    const int w = tid >> 5, lane = tid & 31;
    const int g = lane >> 2, t = lane & 3;
    const int tg = w >> 1, nh = w & 1;
    const int bb = blockIdx.x >> 4;
    const int s0 = (blockIdx.x & 15) * TPB;

    if (tid < TPB)    impS[tid]  = imp[bb * SEQ + s0 + tid];
    if (tid < DSPACE) biasS[tid] = bias[tid];

    // ================= GEMM1: H[128,64] = X[128,1024] @ W + b =================
    // warp tile 32 tok x 32 n; 16 k-chunks of 64, double buffered
    float c1[2][4][4];
    #pragma unroll
    for (int mc = 0; mc < 2; mc++)
        #pragma unroll
        for (int nc = 0; nc < 4; nc++)
            #pragma unroll
            for (int j = 0; j < 4; j++) c1[mc][nc][j] = 0.f;

    const float4* Xg4 = (const float4*)(x + (size_t)(bb * SEQ + s0) * DMODEL);
    const uint4* WHg4 = (const uint4*)g_WH;
    const uint4* WLg4 = (const uint4*)g_WL;
    const int tokS = tid >> 1, hS = tid & 1;
    const int nS = tid >> 2, qS = tid & 3;

    float4 xr[8];
    uint4 wha, whb, wla, wlb;

    #define G1_LDG(cc) do { \
        _Pragma("unroll") \
        for (int i = 0; i < 8; i++) xr[i] = Xg4[(size_t)tokS * 256 + (cc) * 16 + hS * 8 + i]; \
        int ws_ = nS * 128 + (cc) * 8 + qS * 2; \
        wha = WHg4[ws_]; whb = WHg4[ws_ + 1]; \
        wla = WLg4[ws_]; wlb = WLg4[ws_ + 1]; \
    } while (0)

    #define G1_STS(XH_, XL_, WH_, WL_) do { \
        _Pragma("unroll") \
        for (int i = 0; i < 8; i++) { \
            u32 l0, l1; \
            u32 h0 = split2(xr[i].x, xr[i].y, l0); \
            u32 h1 = split2(xr[i].z, xr[i].w, l1); \
            int di = tokS * S36 + hS * 16 + 2 * i; \
            *(ull*)((XH_) + di) = ((ull)h1 << 32) | h0; \
            *(ull*)((XL_) + di) = ((ull)l1 << 32) | l0; \
        } \
        int wd = nS * S36 + qS * 8; \
        *(uint4*)((WH_) + wd) = wha; *(uint4*)((WH_) + wd + 4) = whb; \
        *(uint4*)((WL_) + wd) = wla; *(uint4*)((WL_) + wd + 4) = wlb; \
    } while (0)

    G1_LDG(0);
    G1_STS(XHb[0], XLb[0], WHb[0], WLb[0]);
    __syncthreads();

    for (int c = 0; c < 16; c++) {
        const int par = c & 1;
        if (c < 15) G1_LDG(c + 1);
        // compute chunk
        const u32* XH = XHb[par]; const u32* XL = XLb[par];
        const u32* WH = WHb[par]; const u32* WL = WLb[par];
        #pragma unroll
        for (int ks = 0; ks < 4; ks++) {
            u32 ah[2][4], al[2][4];
            #pragma unroll
            for (int mc = 0; mc < 2; mc++) {
                int r0 = (32 * tg + 16 * mc + g) * S36 + 8 * ks + t;
                ah[mc][0] = XH[r0];     ah[mc][1] = XH[r0 + 8 * S36];
                ah[mc][2] = XH[r0 + 4]; ah[mc][3] = XH[r0 + 8 * S36 + 4];
                al[mc][0] = XL[r0];     al[mc][1] = XL[r0 + 8 * S36];
                al[mc][2] = XL[r0 + 4]; al[mc][3] = XL[r0 + 8 * S36 + 4];
            }
            #pragma unroll
            for (int nc = 0; nc < 4; nc++) {
                int bi = (32 * nh + 8 * nc + g) * S36 + 8 * ks + t;
                u32 bh0 = WH[bi], bh1 = WH[bi + 4];
                u32 bl0 = WL[bi], bl1 = WL[bi + 4];
                #pragma unroll
                for (int mc = 0; mc < 2; mc++) {
                    mma_bf16(c1[mc][nc], ah[mc], bh0, bh1);
                    mma_bf16(c1[mc][nc], ah[mc], bl0, bl1);
                    mma_bf16(c1[mc][nc], al[mc], bh0, bh1);
                }
            }
        }
        __syncthreads();
        if (c < 15) {
            G1_STS(XHb[1 - par], XLb[1 - par], WHb[1 - par], WLb[1 - par]);
            __syncthreads();
        }
    }

    // write H + bias -> A2 (bf16 split, stride-36 u32 rows)
    #pragma unroll
    for (int mc = 0; mc < 2; mc++) {
        int tok = 32 * tg + 16 * mc + g;
        #pragma unroll
        for (int nc = 0; nc < 4; nc++) {
            int col = 32 * nh + 8 * nc + 2 * t;
            int ci  = 16 * nh + 4 * nc + t;
            float b0v = biasS[col], b1v = biasS[col + 1];
            u32 lo, hi;
            hi = split2(c1[mc][nc][0] + b0v, c1[mc][nc][1] + b1v, lo);
            A2H[tok * S36 + ci] = hi;  A2L[tok * S36 + ci] = lo;
            hi = split2(c1[mc][nc][2] + b0v, c1[mc][nc][3] + b1v, lo);
            A2H[(tok + 8) * S36 + ci] = hi;  A2L[(tok + 8) * S36 + ci] = lo;
        }
    }

    // ================= GEMM2 two passes over 4 emb segments =================
    const uint4* EHg4 = (const uint4*)g_embH;
    const uint4* ELg4 = (const uint4*)g_embL;

    for (int pass = 0; pass < 2; pass++) {
        float rs00 = 0.f, rs01 = 0.f, rs10 = 0.f, rs11 = 0.f;
        for (int seg = 0; seg < 4; seg++) {
            __syncthreads();
            int rows = (seg == 3) ? 160 : 256;
            if (tid < rows) {
                const uint4* sH = EHg4 + (size_t)(seg * 256 + tid) * 8;
                const uint4* sL = ELg4 + (size_t)(seg * 256 + tid) * 8;
                uint4* dH = (uint4*)((char*)EH + tid * 144);
                uint4* dL = (uint4*)((char*)EL + tid * 144);
                #pragma unroll
                for (int j = 0; j < 8; j++) { dH[j] = sH[j]; dL[j] = sL[j]; }
            }
            __syncthreads();

            if (seg < 3) {
                const int sl = (seg <= 1) ? 0 : 1;
                float ar00 = 0, ar01 = 0, ar10 = 0, ar11 = 0;
                if (pass == 1) {
                    ar00 = alphaS[sl * 128 + 32 * tg + g];
                    ar01 = alphaS[sl * 128 + 32 * tg + 8 + g];
                    ar10 = alphaS[sl * 128 + 32 * tg + 16 + g];
                    ar11 = alphaS[sl * 128 + 32 * tg + 24 + g];
                }
                for (int i = 0; i < 16; i++) {
                    int n0 = nh * 128 + 8 * i;
                    float c[2][4] = {{0, 0, 0, 0}, {0, 0, 0, 0}};
                    g2_tile(A2H, A2L, EH, EL, tg, g, t, n0, c);
                    if (pass == 0) {
                        rs00 += __expf(c[0][0]) + __expf(c[0][1]);
                        rs01 += __expf(c[0][2]) + __expf(c[0][3]);
                        rs10 += __expf(c[1][0]) + __expf(c[1][1]);
                        rs11 += __expf(c[1][2]) + __expf(c[1][3]);
                    } else {
                        float p0 = ar00 * __expf(c[0][0]) + ar01 * __expf(c[0][2])
                                 + ar10 * __expf(c[1][0]) + ar11 * __expf(c[1][2]);
                        float p1 = ar00 * __expf(c[0][1]) + ar01 * __expf(c[0][3])
                                 + ar10 * __expf(c[1][1]) + ar11 * __expf(c[1][3]);
                        p0 += __shfl_xor_sync(0xffffffffu, p0, 4);
                        p0 += __shfl_xor_sync(0xffffffffu, p0, 8);
                        p0 += __shfl_xor_sync(0xffffffffu, p0, 16);
                        p1 += __shfl_xor_sync(0xffffffffu, p1, 4);
                        p1 += __shfl_xor_sync(0xffffffffu, p1, 8);
                        p1 += __shfl_xor_sync(0xffffffffu, p1, 16);
                        if (lane < 4) {
                            int nabs = seg * 256 + n0 + 2 * t;
                            wacc[tg * N_TOT + nabs]     = p0;
                            wacc[tg * N_TOT + nabs + 1] = p1;
                        }
                    }
                }
                if (pass == 0 && seg >= 1) {
                    // finalize slice sl (0 after seg1, 1 after seg2)
                    rs00 += __shfl_xor_sync(0xffffffffu, rs00, 1); rs00 += __shfl_xor_sync(0xffffffffu, rs00, 2);
                    rs01 += __shfl_xor_sync(0xffffffffu, rs01, 1); rs01 += __shfl_xor_sync(0xffffffffu, rs01, 2);
                    rs10 += __shfl_xor_sync(0xffffffffu, rs10, 1); rs10 += __shfl_xor_sync(0xffffffffu, rs10, 2);
                    rs11 += __shfl_xor_sync(0xffffffffu, rs11, 1); rs11 += __shfl_xor_sync(0xffffffffu, rs11, 2);
                    if (t == 0) {
                        int tokb = nh * 128 + 32 * tg + g;
                        rsS[tokb] = rs00; rsS[tokb + 8] = rs01;
                        rsS[tokb + 16] = rs10; rsS[tokb + 24] = rs11;
                    }
                    __syncthreads();
                    if (tid < 128) alphaS[sl * 128 + tid] = impS[tid] / (rsS[tid] + rsS[128 + tid]);
                    __syncthreads();
                    rs00 = rs01 = rs10 = rs11 = 0.f;
                }
            } else {
                // seg 3: REL (local rows 0..127 -> slice 2), VAL (128..159 -> slice 3)
                for (int part = 0; part < 2; part++) {
                    const int sl = 2 + part;
                    const int base = part ? 128 : 0;
                    const int cnt  = part ? 2 : 8;
                    const int span = part ? 16 : 64;
                    float ar00 = 0, ar01 = 0, ar10 = 0, ar11 = 0;
                    if (pass == 1) {
                        ar00 = alphaS[sl * 128 + 32 * tg + g];
                        ar01 = alphaS[sl * 128 + 32 * tg + 8 + g];
                        ar10 = alphaS[sl * 128 + 32 * tg + 16 + g];
                        ar11 = alphaS[sl * 128 + 32 * tg + 24 + g];
                    }
                    for (int i = 0; i < cnt; i++) {
                        int n0 = base + nh * span + 8 * i;
                        float c[2][4] = {{0, 0, 0, 0}, {0, 0, 0, 0}};
                        g2_tile(A2H, A2L, EH, EL, tg, g, t, n0, c);
                        if (pass == 0) {
                            rs00 += __expf(c[0][0]) + __expf(c[0][1]);
                            rs01 += __expf(c[0][2]) + __expf(c[0][3]);
                            rs10 += __expf(c[1][0]) + __expf(c[1][1]);
                            rs11 += __expf(c[1][2]) + __expf(c[1][3]);
                        } else {
                            float p0 = ar00 * __expf(c[0][0]) + ar01 * __expf(c[0][2])
                                     + ar10 * __expf(c[1][0]) + ar11 * __expf(c[1][2]);
                            float p1 = ar00 * __expf(c[0][1]) + ar01 * __expf(c[0][3])
                                     + ar10 * __expf(c[1][1]) + ar11 * __expf(c[1][3]);
                            p0 += __shfl_xor_sync(0xffffffffu, p0, 4);
                            p0 += __shfl_xor_sync(0xffffffffu, p0, 8);
                            p0 += __shfl_xor_sync(0xffffffffu, p0, 16);
                            p1 += __shfl_xor_sync(0xffffffffu, p1, 4);
                            p1 += __shfl_xor_sync(0xffffffffu, p1, 8);
                            p1 += __shfl_xor_sync(0xffffffffu, p1, 16);
                            if (lane < 4) {
                                int nabs = 768 + n0 + 2 * t;
                                wacc[tg * N_TOT + nabs]     = p0;
                                wacc[tg * N_TOT + nabs + 1] = p1;
                            }
                        }
                    }
                    if (pass == 0) {
                        rs00 += __shfl_xor_sync(0xffffffffu, rs00, 1); rs00 += __shfl_xor_sync(0xffffffffu, rs00, 2);
                        rs01 += __shfl_xor_sync(0xffffffffu, rs01, 1); rs01 += __shfl_xor_sync(0xffffffffu, rs01, 2);
                        rs10 += __shfl_xor_sync(0xffffffffu, rs10, 1); rs10 += __shfl_xor_sync(0xffffffffu, rs10, 2);
                        rs11 += __shfl_xor_sync(0xffffffffu, rs11, 1); rs11 += __shfl_xor_sync(0xffffffffu, rs11, 2);
                        if (t == 0) {
                            int tokb = nh * 128 + 32 * tg + g;
                            rsS[tokb] = rs00; rsS[tokb + 8] = rs01;
                            rsS[tokb + 16] = rs10; rsS[tokb + 24] = rs11;
                        }
                        __syncthreads();
                        if (tid < 128) alphaS[sl * 128 + tid] = impS[tid] / (rsS[tid] + rsS[128 + tid]);
                        __syncthreads();
                        rs00 = rs01 = rs10 = rs11 = 0.f;
                    }
                }
            }
        }
    }
    __syncthreads();

    // combine 4 token-group partials -> per-block partial
    for (int n = tid; n < N_TOT; n += NTHREADS)
        g_wpart[blockIdx.x][n] = wacc[n] + wacc[N_TOT + n] + wacc[2 * N_TOT + n] + wacc[3 * N_TOT + n];

    // ---- completion counter: last block of this batch finalizes ----
    int* lastFlag = (int*)(sm + SM_FLAG);
    __threadfence();
    if (tid == 0) {
        int old = atomicAdd(&g_cnt[bb], 1);
        *lastFlag = (old == 15);
    }
    __syncthreads();
    if (!*lastFlag) return;

    float* sws  = (float*)sm;                 // [928] (aliases A2H, dead now)
    int*   flag = (int*)(sm + 4096);          // [512]
    for (int n = tid; n < N_TOT; n += NTHREADS) {
        float s = 0.0f;
        #pragma unroll
        for (int l = 0; l < 16; l++) s += g_wpart[bb * 16 + l][n];
        sws[n] = s;
    }
    __syncthreads();

    for (int i = tid; i < N_QK; i += NTHREADS) out[OFF_WQK + bb * N_QK + i] = sws[i];
    for (int i = tid; i < N_V;  i += NTHREADS) out[OFF_WV  + bb * N_V  + i] = sws[N_QK + i];

    topk_flags<N_QK, K_QK>(sws, flag, tid);
    __syncthreads();
    for (int i = tid; i < N_QK; i += NTHREADS) {
        if (flag[i]) {
            int pos = 0;
            for (int j = 0; j < i; j++) pos += flag[j];
            out[OFF_IDXQK + bb * K_QK + pos] = (float)i;
        }
    }
    __syncthreads();
    topk_flags<N_V, K_V>(sws + N_QK, flag, tid);
    __syncthreads();
    for (int i = tid; i < N_V; i += NTHREADS) {
        if (flag[i]) {
            int pos = 0;
            for (int j = 0; j < i; j++) pos += flag[j];
            out[OFF_IDXV + bb * K_V + pos] = (float)i;
        }
    }
    __syncthreads();
    topk_flags<N_REL, K_REL>(sws + N_QK + N_V, flag, tid);
    __syncthreads();
    for (int i = tid; i < N_REL; i += NTHREADS) {
        float v = flag[i] ? sws[N_QK + N_V + i] : 0.0f;
        out[OFF_RWQ + bb * N_REL + i] = v;
        out[OFF_RWK + bb * N_REL + i] = v;
    }
    __syncthreads();
    topk_flags<N_VAL, K_VAL>(sws + N_QK + N_V + N_REL, flag, tid);
    __syncthreads();
    for (int i = tid; i < N_VAL; i += NTHREADS)
        out[OFF_VW + bb * N_VAL + i] = flag[i] ? sws[N_QK + N_V + N_REL + i] : 0.0f;
}

extern "C" void kernel_launch(void* const* d_in, const int* in_sizes, int n_in,
                              void* d_out, int out_size) {
    const float* x    = (const float*)d_in[0];
    const float* imp  = (const float*)d_in[1];
    const float* Wm   = (const float*)d_in[2];
    const float* bias = (const float*)d_in[3];
    const float* emb  = (const float*)d_in[4];
    float* out = (float*)d_out;

    cudaFuncSetAttribute(main_kernel, cudaFuncAttributeMaxDynamicSharedMemorySize, SMEM_BYTES);

    prep_emb<<<N_TOT, 64>>>(emb);
    prep_w<<<DSPACE, 256>>>(Wm);
    main_kernel<<<NBLOCKS, NTHREADS, SMEM_BYTES>>>(x, imp, Wm, bias, out);
}

// round 12
// speedup vs baseline: 1.0745x; 1.0745x over previous
#include <cuda_runtime.h>
#include <cuda_bf16.h>
#include <math.h>
#include <string.h>

typedef unsigned long long ull;
typedef unsigned int u32;

// Problem constants
#define BATCH   8
#define SEQ     2048
#define DMODEL  1024
#define DSPACE  64
#define N_QK    512
#define N_V     256
#define N_REL   128
#define N_VAL   32
#define N_TOT   928
#define K_QK    64
#define K_V     32
#define K_REL   16
#define K_VAL   3

#define TPB      128
#define NTHREADS 256
#define NBLOCKS  128               // 16 per batch

// Output layout (float32, reference return order)
#define OFF_IDXQK 0
#define OFF_IDXV  (OFF_IDXQK + BATCH*K_QK)
#define OFF_RWQ   (OFF_IDXV  + BATCH*K_V)
#define OFF_RWK   (OFF_RWQ   + BATCH*N_REL)
#define OFF_VW    (OFF_RWK   + BATCH*N_REL)
#define OFF_WQK   (OFF_VW    + BATCH*N_VAL)
#define OFF_WV    (OFF_WQK   + BATCH*N_QK)

// u32-stride for all MMA smem tiles (32 payload + 4 pad) -> conflict-free frags
#define S36 36

// Shared memory byte offsets
#define SM_A2H   0          // u32[128][36] H hi  (18432)
#define SM_A2L   18432      // u32[128][36] H lo  (18432)
// staging region @36864:
//   GEMM1 buf0: XH 36864(18432) XL 55296(18432) WH 73728(9216) WL 82944(9216)
//   GEMM1 buf1: XH 92160 XL 110592 WH 129024 WL 138240  (end 147456)
//   GEMM2 emb:  EH 36864 (256*36*4=36864)  EL 73728     (end 110592)
//   finalize: sws @0 (aliases A2H), flag @4096
#define SM_EH    36864
#define SM_EL    73728
#define SM_WACC  147456     // float[4][928] = 14848
#define SM_IMP   162304     // float[128]
#define SM_BIAS  162816     // float[64]
#define SM_RS    163072     // float[256]
#define SM_ALPHA 164096     // float[4][128]
#define SM_FLAG  166144
#define SMEM_BYTES 166400

// device scratch (no allocation allowed)
__device__ u32 g_embH[N_TOT * 32];    // bf16 pairs [n][k2], k2 = d/2
__device__ u32 g_embL[N_TOT * 32];
__device__ u32 g_WH[DSPACE * 512];    // bf16 pairs [n=dspace][k2], k2 = k/2
__device__ u32 g_WL[DSPACE * 512];
__device__ float g_wpart[NBLOCKS][N_TOT];
__device__ int   g_cnt[BATCH];

// ---------------- helpers ----------------
// fp32 pair -> bf16x2 hi (return) / lo (out param); low 16 bits = first elem
__device__ __forceinline__ u32 split2(float a, float b, u32& lo) {
    __nv_bfloat162 h = __floats2bfloat162_rn(a, b);
    float ha = __low2float(h), hb = __high2float(h);
    __nv_bfloat162 l = __floats2bfloat162_rn(a - ha, b - hb);
    u32 uh, ul;
    memcpy(&uh, &h, 4);
    memcpy(&ul, &l, 4);
    lo = ul;
    return uh;
}

__device__ __forceinline__ void mma_bf16(float* c, const u32* a, u32 b0, u32 b1) {
    asm volatile(
        "mma.sync.aligned.m16n8k16.row.col.f32.bf16.bf16.f32 "
        "{%0,%1,%2,%3}, {%4,%5,%6,%7}, {%8,%9}, {%0,%1,%2,%3};"
        : "+f"(c[0]), "+f"(c[1]), "+f"(c[2]), "+f"(c[3])
        : "r"(a[0]), "r"(a[1]), "r"(a[2]), "r"(a[3]), "r"(b0), "r"(b1));
}

// ---------------- prep kernels ----------------
__global__ void prep_emb(const float* __restrict__ emb) {
    int r = blockIdx.x;     // neuron
    int t = threadIdx.x;    // dim
    __shared__ float s[64];
    __shared__ float e[64];
    float v = emb[r * DSPACE + t];
    s[t] = v * v;
    __syncthreads();
    #pragma unroll
    for (int o = 32; o > 0; o >>= 1) {
        if (t < o) s[t] += s[t + o];
        __syncthreads();
    }
    e[t] = v / sqrtf(s[0]);
    __syncthreads();
    if (t < 32) {
        u32 lo, hi = split2(e[2 * t], e[2 * t + 1], lo);
        g_embH[r * 32 + t] = hi;
        g_embL[r * 32 + t] = lo;
    }
}

__global__ void prep_w(const float* __restrict__ W) {
    int n = blockIdx.x;     // dspace col
    int tid = threadIdx.x;
    if (n == 0 && tid < BATCH) g_cnt[tid] = 0;
    for (int k2 = tid; k2 < 512; k2 += 256) {
        float a = W[(size_t)(2 * k2) * DSPACE + n];
        float b = W[(size_t)(2 * k2 + 1) * DSPACE + n];
        u32 lo, hi = split2(a, b, lo);
        g_WH[n * 512 + k2] = hi;
        g_WL[n * 512 + k2] = lo;
    }
}

// ---------------- finalize helper ----------------
template<int NN, int KK>
__device__ __forceinline__ void topk_flags(const float* ws, int* flag, int tid) {
    for (int i = tid; i < NN; i += NTHREADS) {
        float wi = ws[i]; int r = 0;
        #pragma unroll 16
        for (int j = 0; j < NN; j++) {
            float wj = ws[j];
            r += (wj > wi) || (wj == wi && j < i);
        }
        flag[i] = (r < KK) ? 1 : 0;
    }
}

// ---------------- GEMM2 tile with register-resident A-fragments ----------------
// AH/AL: [mc][ks][4] hoisted fragments; B from SMEM (16 LDS per 24 MMAs)
__device__ __forceinline__ void g2_tile_r(const u32 AH[2][4][4], const u32 AL[2][4][4],
                                          const u32* __restrict__ EH, const u32* __restrict__ EL,
                                          int g, int t, int n0loc, float c[2][4]) {
    #pragma unroll
    for (int ks = 0; ks < 4; ks++) {
        int bi = (n0loc + g) * S36 + 8 * ks + t;
        u32 bh0 = EH[bi], bh1 = EH[bi + 4];
        u32 bl0 = EL[bi], bl1 = EL[bi + 4];
        #pragma unroll
        for (int mc = 0; mc < 2; mc++) {
            mma_bf16(c[mc], AH[mc][ks], bh0, bh1);
            mma_bf16(c[mc], AH[mc][ks], bl0, bl1);
            mma_bf16(c[mc], AL[mc][ks], bh0, bh1);
        }
    }
}

// ---------------- main fused kernel ----------------
__global__ void __launch_bounds__(NTHREADS, 1)
main_kernel(const float* __restrict__ x, const float* __restrict__ imp,
            const float* __restrict__ Wm, const float* __restrict__ bias,
            float* __restrict__ out)
{
    extern __shared__ char sm[];
    u32* A2H = (u32*)(sm + SM_A2H);
    u32* A2L = (u32*)(sm + SM_A2L);
    u32* EH  = (u32*)(sm + SM_EH);
    u32* EL  = (u32*)(sm + SM_EL);
    float* wacc   = (float*)(sm + SM_WACC);
    float* impS   = (float*)(sm + SM_IMP);
    float* biasS  = (float*)(sm + SM_BIAS);
    float* rsS    = (float*)(sm + SM_RS);
    float* alphaS = (float*)(sm + SM_ALPHA);

    u32* XHb[2] = {(u32*)(sm + 36864), (u32*)(sm + 92160)};
    u32* XLb[2] = {(u32*)(sm + 55296), (u32*)(sm + 110592)};
    u32* WHb[2] = {(u32*)(sm + 73728), (u32*)(sm + 129024)};
    u32* WLb[2] = {(u32*)(sm + 82944), (u32*)(sm + 138240)};

    const int tid = threadIdx.x;
    const int w = tid >> 5, lane = tid & 31;
    const int g = lane >> 2, t = lane & 3;
    const int tg = w >> 1, nh = w & 1;
    const int bb = blockIdx.x >> 4;
    const int s0 = (blockIdx.x & 15) * TPB;

    if (tid < TPB)    impS[tid]  = imp[bb * SEQ + s0 + tid];
    if (tid < DSPACE) biasS[tid] = bias[tid];

    // ================= GEMM1: H[128,64] = X[128,1024] @ W + b =================
    float c1[2][4][4];
    #pragma unroll
    for (int mc = 0; mc < 2; mc++)
        #pragma unroll
        for (int nc = 0; nc < 4; nc++)
            #pragma unroll
            for (int j = 0; j < 4; j++) c1[mc][nc][j] = 0.f;

    const float4* Xg4 = (const float4*)(x + (size_t)(bb * SEQ + s0) * DMODEL);
    const uint4* WHg4 = (const uint4*)g_WH;
    const uint4* WLg4 = (const uint4*)g_WL;
    const int tokS = tid >> 1, hS = tid & 1;
    const int nS = tid >> 2, qS = tid & 3;

    float4 xr[8];
    uint4 wha, whb, wla, wlb;

    #define G1_LDG(cc) do { \
        _Pragma("unroll") \
        for (int i = 0; i < 8; i++) xr[i] = Xg4[(size_t)tokS * 256 + (cc) * 16 + hS * 8 + i]; \
        int ws_ = nS * 128 + (cc) * 8 + qS * 2; \
        wha = WHg4[ws_]; whb = WHg4[ws_ + 1]; \
        wla = WLg4[ws_]; wlb = WLg4[ws_ + 1]; \
    } while (0)

    #define G1_STS(XH_, XL_, WH_, WL_) do { \
        _Pragma("unroll") \
        for (int i = 0; i < 8; i++) { \
            u32 l0, l1; \
            u32 h0 = split2(xr[i].x, xr[i].y, l0); \
            u32 h1 = split2(xr[i].z, xr[i].w, l1); \
            int di = tokS * S36 + hS * 16 + 2 * i; \
            *(ull*)((XH_) + di) = ((ull)h1 << 32) | h0; \
            *(ull*)((XL_) + di) = ((ull)l1 << 32) | l0; \
        } \
        int wd = nS * S36 + qS * 8; \
        *(uint4*)((WH_) + wd) = wha; *(uint4*)((WH_) + wd + 4) = whb; \
        *(uint4*)((WL_) + wd) = wla; *(uint4*)((WL_) + wd + 4) = wlb; \
    } while (0)

    G1_LDG(0);
    G1_STS(XHb[0], XLb[0], WHb[0], WLb[0]);
    __syncthreads();

    for (int c = 0; c < 16; c++) {
        const int par = c & 1;
        if (c < 15) G1_LDG(c + 1);
        const u32* XH = XHb[par]; const u32* XL = XLb[par];
        const u32* WH = WHb[par]; const u32* WL = WLb[par];
        #pragma unroll
        for (int ks = 0; ks < 4; ks++) {
            u32 ah[2][4], al[2][4];
            #pragma unroll
            for (int mc = 0; mc < 2; mc++) {
                int r0 = (32 * tg + 16 * mc + g) * S36 + 8 * ks + t;
                ah[mc][0] = XH[r0];     ah[mc][1] = XH[r0 + 8 * S36];
                ah[mc][2] = XH[r0 + 4]; ah[mc][3] = XH[r0 + 8 * S36 + 4];
                al[mc][0] = XL[r0];     al[mc][1] = XL[r0 + 8 * S36];
                al[mc][2] = XL[r0 + 4]; al[mc][3] = XL[r0 + 8 * S36 + 4];
            }
            #pragma unroll
            for (int nc = 0; nc < 4; nc++) {
                int bi = (32 * nh + 8 * nc + g) * S36 + 8 * ks + t;
                u32 bh0 = WH[bi], bh1 = WH[bi + 4];
                u32 bl0 = WL[bi], bl1 = WL[bi + 4];
                #pragma unroll
                for (int mc = 0; mc < 2; mc++) {
                    mma_bf16(c1[mc][nc], ah[mc], bh0, bh1);
                    mma_bf16(c1[mc][nc], ah[mc], bl0, bl1);
                    mma_bf16(c1[mc][nc], al[mc], bh0, bh1);
                }
            }
        }
        __syncthreads();
        if (c < 15) {
            G1_STS(XHb[1 - par], XLb[1 - par], WHb[1 - par], WLb[1 - par]);
            __syncthreads();
        }
    }

    // write H + bias -> A2 (bf16 split, stride-36 u32 rows)
    #pragma unroll
    for (int mc = 0; mc < 2; mc++) {
        int tok = 32 * tg + 16 * mc + g;
        #pragma unroll
        for (int nc = 0; nc < 4; nc++) {
            int col = 32 * nh + 8 * nc + 2 * t;
            int ci  = 16 * nh + 4 * nc + t;
            float b0v = biasS[col], b1v = biasS[col + 1];
            u32 lo, hi;
            hi = split2(c1[mc][nc][0] + b0v, c1[mc][nc][1] + b1v, lo);
            A2H[tok * S36 + ci] = hi;  A2L[tok * S36 + ci] = lo;
            hi = split2(c1[mc][nc][2] + b0v, c1[mc][nc][3] + b1v, lo);
            A2H[(tok + 8) * S36 + ci] = hi;  A2L[(tok + 8) * S36 + ci] = lo;
        }
    }
    __syncthreads();

    // ===== hoist A-fragments into registers (invariant for all of GEMM2) =====
    u32 AH[2][4][4], AL[2][4][4];
    #pragma unroll
    for (int mc = 0; mc < 2; mc++)
        #pragma unroll
        for (int ks = 0; ks < 4; ks++) {
            int r0 = (32 * tg + 16 * mc + g) * S36 + 8 * ks + t;
            AH[mc][ks][0] = A2H[r0];     AH[mc][ks][1] = A2H[r0 + 8 * S36];
            AH[mc][ks][2] = A2H[r0 + 4]; AH[mc][ks][3] = A2H[r0 + 8 * S36 + 4];
            AL[mc][ks][0] = A2L[r0];     AL[mc][ks][1] = A2L[r0 + 8 * S36];
            AL[mc][ks][2] = A2L[r0 + 4]; AL[mc][ks][3] = A2L[r0 + 8 * S36 + 4];
        }

    // ================= GEMM2 two passes over 4 emb segments =================
    const uint4* EHg4 = (const uint4*)g_embH;
    const uint4* ELg4 = (const uint4*)g_embL;

    for (int pass = 0; pass < 2; pass++) {
        float rs00 = 0.f, rs01 = 0.f, rs10 = 0.f, rs11 = 0.f;
        for (int seg = 0; seg < 4; seg++) {
            __syncthreads();
            int rows = (seg == 3) ? 160 : 256;
            if (tid < rows) {
                const uint4* sH = EHg4 + (size_t)(seg * 256 + tid) * 8;
                const uint4* sL = ELg4 + (size_t)(seg * 256 + tid) * 8;
                uint4* dH = (uint4*)((char*)EH + tid * 144);
                uint4* dL = (uint4*)((char*)EL + tid * 144);
                #pragma unroll
                for (int j = 0; j < 8; j++) { dH[j] = sH[j]; dL[j] = sL[j]; }
            }
            __syncthreads();

            if (seg < 3) {
                const int sl = (seg <= 1) ? 0 : 1;
                float ar00 = 0, ar01 = 0, ar10 = 0, ar11 = 0;
                if (pass == 1) {
                    ar00 = alphaS[sl * 128 + 32 * tg + g];
                    ar01 = alphaS[sl * 128 + 32 * tg + 8 + g];
                    ar10 = alphaS[sl * 128 + 32 * tg + 16 + g];
                    ar11 = alphaS[sl * 128 + 32 * tg + 24 + g];
                }
                for (int i = 0; i < 16; i++) {
                    int n0 = nh * 128 + 8 * i;
                    float c[2][4] = {{0, 0, 0, 0}, {0, 0, 0, 0}};
                    g2_tile_r(AH, AL, EH, EL, g, t, n0, c);
                    if (pass == 0) {
                        rs00 += __expf(c[0][0]) + __expf(c[0][1]);
                        rs01 += __expf(c[0][2]) + __expf(c[0][3]);
                        rs10 += __expf(c[1][0]) + __expf(c[1][1]);
                        rs11 += __expf(c[1][2]) + __expf(c[1][3]);
                    } else {
                        float p0 = ar00 * __expf(c[0][0]) + ar01 * __expf(c[0][2])
                                 + ar10 * __expf(c[1][0]) + ar11 * __expf(c[1][2]);
                        float p1 = ar00 * __expf(c[0][1]) + ar01 * __expf(c[0][3])
                                 + ar10 * __expf(c[1][1]) + ar11 * __expf(c[1][3]);
                        p0 += __shfl_xor_sync(0xffffffffu, p0, 4);
                        p0 += __shfl_xor_sync(0xffffffffu, p0, 8);
                        p0 += __shfl_xor_sync(0xffffffffu, p0, 16);
                        p1 += __shfl_xor_sync(0xffffffffu, p1, 4);
                        p1 += __shfl_xor_sync(0xffffffffu, p1, 8);
                        p1 += __shfl_xor_sync(0xffffffffu, p1, 16);
                        if (lane < 4) {
                            int nabs = seg * 256 + n0 + 2 * t;
                            wacc[tg * N_TOT + nabs]     = p0;
                            wacc[tg * N_TOT + nabs + 1] = p1;
                        }
                    }
                }
                if (pass == 0 && seg >= 1) {
                    rs00 += __shfl_xor_sync(0xffffffffu, rs00, 1); rs00 += __shfl_xor_sync(0xffffffffu, rs00, 2);
                    rs01 += __shfl_xor_sync(0xffffffffu, rs01, 1); rs01 += __shfl_xor_sync(0xffffffffu, rs01, 2);
                    rs10 += __shfl_xor_sync(0xffffffffu, rs10, 1); rs10 += __shfl_xor_sync(0xffffffffu, rs10, 2);
                    rs11 += __shfl_xor_sync(0xffffffffu, rs11, 1); rs11 += __shfl_xor_sync(0xffffffffu, rs11, 2);
                    if (t == 0) {
                        int tokb = nh * 128 + 32 * tg + g;
                        rsS[tokb] = rs00; rsS[tokb + 8] = rs01;
                        rsS[tokb + 16] = rs10; rsS[tokb + 24] = rs11;
                    }
                    __syncthreads();
                    if (tid < 128) alphaS[sl * 128 + tid] = impS[tid] / (rsS[tid] + rsS[128 + tid]);
                    __syncthreads();
                    rs00 = rs01 = rs10 = rs11 = 0.f;
                }
            } else {
                for (int part = 0; part < 2; part++) {
                    const int sl = 2 + part;
                    const int base = part ? 128 : 0;
                    const int cnt  = part ? 2 : 8;
                    const int span = part ? 16 : 64;
                    float ar00 = 0, ar01 = 0, ar10 = 0, ar11 = 0;
                    if (pass == 1) {
                        ar00 = alphaS[sl * 128 + 32 * tg + g];
                        ar01 = alphaS[sl * 128 + 32 * tg + 8 + g];
                        ar10 = alphaS[sl * 128 + 32 * tg + 16 + g];
                        ar11 = alphaS[sl * 128 + 32 * tg + 24 + g];
                    }
                    for (int i = 0; i < cnt; i++) {
                        int n0 = base + nh * span + 8 * i;
                        float c[2][4] = {{0, 0, 0, 0}, {0, 0, 0, 0}};
                        g2_tile_r(AH, AL, EH, EL, g, t, n0, c);
                        if (pass == 0) {
                            rs00 += __expf(c[0][0]) + __expf(c[0][1]);
                            rs01 += __expf(c[0][2]) + __expf(c[0][3]);
                            rs10 += __expf(c[1][0]) + __expf(c[1][1]);
                            rs11 += __expf(c[1][2]) + __expf(c[1][3]);
                        } else {
                            float p0 = ar00 * __expf(c[0][0]) + ar01 * __expf(c[0][2])
                                     + ar10 * __expf(c[1][0]) + ar11 * __expf(c[1][2]);
                            float p1 = ar00 * __expf(c[0][1]) + ar01 * __expf(c[0][3])
                                     + ar10 * __expf(c[1][1]) + ar11 * __expf(c[1][3]);
                            p0 += __shfl_xor_sync(0xffffffffu, p0, 4);
                            p0 += __shfl_xor_sync(0xffffffffu, p0, 8);
                            p0 += __shfl_xor_sync(0xffffffffu, p0, 16);
                            p1 += __shfl_xor_sync(0xffffffffu, p1, 4);
                            p1 += __shfl_xor_sync(0xffffffffu, p1, 8);
                            p1 += __shfl_xor_sync(0xffffffffu, p1, 16);
                            if (lane < 4) {
                                int nabs = 768 + n0 + 2 * t;
                                wacc[tg * N_TOT + nabs]     = p0;
                                wacc[tg * N_TOT + nabs + 1] = p1;
                            }
                        }
                    }
                    if (pass == 0) {
                        rs00 += __shfl_xor_sync(0xffffffffu, rs00, 1); rs00 += __shfl_xor_sync(0xffffffffu, rs00, 2);
                        rs01 += __shfl_xor_sync(0xffffffffu, rs01, 1); rs01 += __shfl_xor_sync(0xffffffffu, rs01, 2);
                        rs10 += __shfl_xor_sync(0xffffffffu, rs10, 1); rs10 += __shfl_xor_sync(0xffffffffu, rs10, 2);
                        rs11 += __shfl_xor_sync(0xffffffffu, rs11, 1); rs11 += __shfl_xor_sync(0xffffffffu, rs11, 2);
                        if (t == 0) {
                            int tokb = nh * 128 + 32 * tg + g;
                            rsS[tokb] = rs00; rsS[tokb + 8] = rs01;
                            rsS[tokb + 16] = rs10; rsS[tokb + 24] = rs11;
                        }
                        __syncthreads();
                        if (tid < 128) alphaS[sl * 128 + tid] = impS[tid] / (rsS[tid] + rsS[128 + tid]);
                        __syncthreads();
                        rs00 = rs01 = rs10 = rs11 = 0.f;
                    }
                }
            }
        }
    }
    __syncthreads();

    // combine 4 token-group partials -> per-block partial
    for (int n = tid; n < N_TOT; n += NTHREADS)
        g_wpart[blockIdx.x][n] = wacc[n] + wacc[N_TOT + n] + wacc[2 * N_TOT + n] + wacc[3 * N_TOT + n];

    // ---- completion counter: last block of this batch finalizes ----
    int* lastFlag = (int*)(sm + SM_FLAG);
    __threadfence();
    if (tid == 0) {
        int old = atomicAdd(&g_cnt[bb], 1);
        *lastFlag = (old == 15);
    }
    __syncthreads();
    if (!*lastFlag) return;

    float* sws  = (float*)sm;                 // [928] (aliases A2H, dead now)
    int*   flag = (int*)(sm + 4096);          // [512]
    for (int n = tid; n < N_TOT; n += NTHREADS) {
        float s = 0.0f;
        #pragma unroll
        for (int l = 0; l < 16; l++) s += g_wpart[bb * 16 + l][n];
        sws[n] = s;
    }
    __syncthreads();

    for (int i = tid; i < N_QK; i += NTHREADS) out[OFF_WQK + bb * N_QK + i] = sws[i];
    for (int i = tid; i < N_V;  i += NTHREADS) out[OFF_WV  + bb * N_V  + i] = sws[N_QK + i];

    topk_flags<N_QK, K_QK>(sws, flag, tid);
    __syncthreads();
    for (int i = tid; i < N_QK; i += NTHREADS) {
        if (flag[i]) {
            int pos = 0;
            for (int j = 0; j < i; j++) pos += flag[j];
            out[OFF_IDXQK + bb * K_QK + pos] = (float)i;
        }
    }
    __syncthreads();
    topk_flags<N_V, K_V>(sws + N_QK, flag, tid);
    __syncthreads();
    for (int i = tid; i < N_V; i += NTHREADS) {
        if (flag[i]) {
            int pos = 0;
            for (int j = 0; j < i; j++) pos += flag[j];
            out[OFF_IDXV + bb * K_V + pos] = (float)i;
        }
    }
    __syncthreads();
    topk_flags<N_REL, K_REL>(sws + N_QK + N_V, flag, tid);
    __syncthreads();
    for (int i = tid; i < N_REL; i += NTHREADS) {
        float v = flag[i] ? sws[N_QK + N_V + i] : 0.0f;
        out[OFF_RWQ + bb * N_REL + i] = v;
        out[OFF_RWK + bb * N_REL + i] = v;
    }
    __syncthreads();
    topk_flags<N_VAL, K_VAL>(sws + N_QK + N_V + N_REL, flag, tid);
    __syncthreads();
    for (int i = tid; i < N_VAL; i += NTHREADS)
        out[OFF_VW + bb * N_VAL + i] = flag[i] ? sws[N_QK + N_V + N_REL + i] : 0.0f;
}

extern "C" void kernel_launch(void* const* d_in, const int* in_sizes, int n_in,
                              void* d_out, int out_size) {
    const float* x    = (const float*)d_in[0];
    const float* imp  = (const float*)d_in[1];
    const float* Wm   = (const float*)d_in[2];
    const float* bias = (const float*)d_in[3];
    const float* emb  = (const float*)d_in[4];
    float* out = (float*)d_out;

    cudaFuncSetAttribute(main_kernel, cudaFuncAttributeMaxDynamicSharedMemorySize, SMEM_BYTES);

    prep_emb<<<N_TOT, 64>>>(emb);
    prep_w<<<DSPACE, 256>>>(Wm);
    main_kernel<<<NBLOCKS, NTHREADS, SMEM_BYTES>>>(x, imp, Wm, bias, out);
}

// round 13
// speedup vs baseline: 1.1267x; 1.0486x over previous
#include <cuda_runtime.h>
#include <cuda_bf16.h>
#include <math.h>
#include <string.h>

typedef unsigned long long ull;
typedef unsigned int u32;

// Problem constants
#define BATCH   8
#define SEQ     2048
#define DMODEL  1024
#define DSPACE  64
#define N_QK    512
#define N_V     256
#define N_REL   128
#define N_VAL   32
#define N_TOT   928
#define K_QK    64
#define K_V     32
#define K_REL   16
#define K_VAL   3

#define TPB      128
#define NTHREADS 256
#define NBLOCKS  128               // 16 per batch

// Output layout (float32, reference return order)
#define OFF_IDXQK 0
#define OFF_IDXV  (OFF_IDXQK + BATCH*K_QK)
#define OFF_RWQ   (OFF_IDXV  + BATCH*K_V)
#define OFF_RWK   (OFF_RWQ   + BATCH*N_REL)
#define OFF_VW    (OFF_RWK   + BATCH*N_REL)
#define OFF_WQK   (OFF_VW    + BATCH*N_VAL)
#define OFF_WV    (OFF_WQK   + BATCH*N_QK)

// u32-stride for all MMA smem tiles (32 payload + 4 pad) -> conflict-free frags
#define S36 36

// Shared memory byte offsets
#define SM_A2H   0          // u32[128][36] H hi  (18432)
#define SM_A2L   18432      // u32[128][36] H lo  (18432)
// staging region @36864:
//   GEMM1 buf0: XH 36864(18432) XL 55296(18432) WH 73728(9216) WL 82944(9216)
//   GEMM1 buf1: XH 92160 XL 110592 WH 129024 WL 138240  (end 147456)
//   GEMM2 emb:  EH 36864 (256*36*4=36864)  EL 73728     (end 110592)
//   finalize: sws @0 (aliases A2H), flag @4096
#define SM_EH    36864
#define SM_EL    73728
#define SM_IMP   147456     // float[128]
#define SM_BIAS  147968     // float[64]
#define SM_RS    148224     // float[256]
#define SM_ALPHA 149248     // float[4][128]
#define SM_FLAG  151296
#define SMEM_BYTES 151552

// device scratch (no allocation allowed)
__device__ u32 g_embH[N_TOT * 32];    // bf16 pairs [n][k2], k2 = d/2
__device__ u32 g_embL[N_TOT * 32];
__device__ u32 g_WH[DSPACE * 512];    // bf16 pairs [n=dspace][k2]
__device__ u32 g_WL[DSPACE * 512];
__device__ float g_e[NBLOCKS][TPB * N_TOT];   // per-block exp scratch (61 MB)
__device__ float g_wpart[NBLOCKS][N_TOT];
__device__ int   g_cnt[BATCH];

// ---------------- helpers ----------------
__device__ __forceinline__ u32 split2(float a, float b, u32& lo) {
    __nv_bfloat162 h = __floats2bfloat162_rn(a, b);
    float ha = __low2float(h), hb = __high2float(h);
    __nv_bfloat162 l = __floats2bfloat162_rn(a - ha, b - hb);
    u32 uh, ul;
    memcpy(&uh, &h, 4);
    memcpy(&ul, &l, 4);
    lo = ul;
    return uh;
}

__device__ __forceinline__ void mma_bf16(float* c, const u32* a, u32 b0, u32 b1) {
    asm volatile(
        "mma.sync.aligned.m16n8k16.row.col.f32.bf16.bf16.f32 "
        "{%0,%1,%2,%3}, {%4,%5,%6,%7}, {%8,%9}, {%0,%1,%2,%3};"
        : "+f"(c[0]), "+f"(c[1]), "+f"(c[2]), "+f"(c[3])
        : "r"(a[0]), "r"(a[1]), "r"(a[2]), "r"(a[3]), "r"(b0), "r"(b1));
}

// ---------------- prep kernels ----------------
__global__ void prep_emb(const float* __restrict__ emb) {
    int r = blockIdx.x;
    int t = threadIdx.x;
    __shared__ float s[64];
    __shared__ float e[64];
    float v = emb[r * DSPACE + t];
    s[t] = v * v;
    __syncthreads();
    #pragma unroll
    for (int o = 32; o > 0; o >>= 1) {
        if (t < o) s[t] += s[t + o];
        __syncthreads();
    }
    e[t] = v / sqrtf(s[0]);
    __syncthreads();
    if (t < 32) {
        u32 lo, hi = split2(e[2 * t], e[2 * t + 1], lo);
        g_embH[r * 32 + t] = hi;
        g_embL[r * 32 + t] = lo;
    }
}

__global__ void prep_w(const float* __restrict__ W) {
    int n = blockIdx.x;
    int tid = threadIdx.x;
    if (n == 0 && tid < BATCH) g_cnt[tid] = 0;
    for (int k2 = tid; k2 < 512; k2 += 256) {
        float a = W[(size_t)(2 * k2) * DSPACE + n];
        float b = W[(size_t)(2 * k2 + 1) * DSPACE + n];
        u32 lo, hi = split2(a, b, lo);
        g_WH[n * 512 + k2] = hi;
        g_WL[n * 512 + k2] = lo;
    }
}

// ---------------- finalize helper ----------------
template<int NN, int KK>
__device__ __forceinline__ void topk_flags(const float* ws, int* flag, int tid) {
    for (int i = tid; i < NN; i += NTHREADS) {
        float wi = ws[i]; int r = 0;
        #pragma unroll 16
        for (int j = 0; j < NN; j++) {
            float wj = ws[j];
            r += (wj > wi) || (wj == wi && j < i);
        }
        flag[i] = (r < KK) ? 1 : 0;
    }
}

// ---------------- GEMM2 tile with register-resident A-fragments ----------------
__device__ __forceinline__ void g2_tile_r(const u32 AH[2][4][4], const u32 AL[2][4][4],
                                          const u32* __restrict__ EH, const u32* __restrict__ EL,
                                          int g, int t, int n0loc, float c[2][4]) {
    #pragma unroll
    for (int ks = 0; ks < 4; ks++) {
        int bi = (n0loc + g) * S36 + 8 * ks + t;
        u32 bh0 = EH[bi], bh1 = EH[bi + 4];
        u32 bl0 = EL[bi], bl1 = EL[bi + 4];
        #pragma unroll
        for (int mc = 0; mc < 2; mc++) {
            mma_bf16(c[mc], AH[mc][ks], bh0, bh1);
            mma_bf16(c[mc], AH[mc][ks], bl0, bl1);
            mma_bf16(c[mc], AL[mc][ks], bh0, bh1);
        }
    }
}

// ---------------- main fused kernel ----------------
__global__ void __launch_bounds__(NTHREADS, 1)
main_kernel(const float* __restrict__ x, const float* __restrict__ imp,
            const float* __restrict__ Wm, const float* __restrict__ bias,
            float* __restrict__ out)
{
    extern __shared__ char sm[];
    u32* A2H = (u32*)(sm + SM_A2H);
    u32* A2L = (u32*)(sm + SM_A2L);
    u32* EH  = (u32*)(sm + SM_EH);
    u32* EL  = (u32*)(sm + SM_EL);
    float* impS   = (float*)(sm + SM_IMP);
    float* biasS  = (float*)(sm + SM_BIAS);
    float* rsS    = (float*)(sm + SM_RS);
    float* alphaS = (float*)(sm + SM_ALPHA);

    u32* XHb[2] = {(u32*)(sm + 36864), (u32*)(sm + 92160)};
    u32* XLb[2] = {(u32*)(sm + 55296), (u32*)(sm + 110592)};
    u32* WHb[2] = {(u32*)(sm + 73728), (u32*)(sm + 129024)};
    u32* WLb[2] = {(u32*)(sm + 82944), (u32*)(sm + 138240)};

    const int tid = threadIdx.x;
    const int w = tid >> 5, lane = tid & 31;
    const int g = lane >> 2, t = lane & 3;
    const int tg = w >> 1, nh = w & 1;
    const int bb = blockIdx.x >> 4;
    const int s0 = (blockIdx.x & 15) * TPB;
    float* geb = g_e[blockIdx.x];

    if (tid < TPB)    impS[tid]  = imp[bb * SEQ + s0 + tid];
    if (tid < DSPACE) biasS[tid] = bias[tid];

    // ================= GEMM1: H[128,64] = X[128,1024] @ W + b =================
    float c1[2][4][4];
    #pragma unroll
    for (int mc = 0; mc < 2; mc++)
        #pragma unroll
        for (int nc = 0; nc < 4; nc++)
            #pragma unroll
            for (int j = 0; j < 4; j++) c1[mc][nc][j] = 0.f;

    const float4* Xg4 = (const float4*)(x + (size_t)(bb * SEQ + s0) * DMODEL);
    const uint4* WHg4 = (const uint4*)g_WH;
    const uint4* WLg4 = (const uint4*)g_WL;
    const int tokS = tid >> 1, hS = tid & 1;
    const int nS = tid >> 2, qS = tid & 3;

    float4 xr[8];
    uint4 wha, whb, wla, wlb;

    #define G1_LDG(cc) do { \
        _Pragma("unroll") \
        for (int i = 0; i < 8; i++) xr[i] = Xg4[(size_t)tokS * 256 + (cc) * 16 + hS * 8 + i]; \
        int ws_ = nS * 128 + (cc) * 8 + qS * 2; \
        wha = WHg4[ws_]; whb = WHg4[ws_ + 1]; \
        wla = WLg4[ws_]; wlb = WLg4[ws_ + 1]; \
    } while (0)

    #define G1_STS(XH_, XL_, WH_, WL_) do { \
        _Pragma("unroll") \
        for (int i = 0; i < 8; i++) { \
            u32 l0, l1; \
            u32 h0 = split2(xr[i].x, xr[i].y, l0); \
            u32 h1 = split2(xr[i].z, xr[i].w, l1); \
            int di = tokS * S36 + hS * 16 + 2 * i; \
            *(ull*)((XH_) + di) = ((ull)h1 << 32) | h0; \
            *(ull*)((XL_) + di) = ((ull)l1 << 32) | l0; \
        } \
        int wd = nS * S36 + qS * 8; \
        *(uint4*)((WH_) + wd) = wha; *(uint4*)((WH_) + wd + 4) = whb; \
        *(uint4*)((WL_) + wd) = wla; *(uint4*)((WL_) + wd + 4) = wlb; \
    } while (0)

    G1_LDG(0);
    G1_STS(XHb[0], XLb[0], WHb[0], WLb[0]);
    __syncthreads();

    for (int c = 0; c < 16; c++) {
        const int par = c & 1;
        if (c < 15) G1_LDG(c + 1);
        const u32* XH = XHb[par]; const u32* XL = XLb[par];
        const u32* WH = WHb[par]; const u32* WL = WLb[par];
        #pragma unroll
        for (int ks = 0; ks < 4; ks++) {
            u32 ah[2][4], al[2][4];
            #pragma unroll
            for (int mc = 0; mc < 2; mc++) {
                int r0 = (32 * tg + 16 * mc + g) * S36 + 8 * ks + t;
                ah[mc][0] = XH[r0];     ah[mc][1] = XH[r0 + 8 * S36];
                ah[mc][2] = XH[r0 + 4]; ah[mc][3] = XH[r0 + 8 * S36 + 4];
                al[mc][0] = XL[r0];     al[mc][1] = XL[r0 + 8 * S36];
                al[mc][2] = XL[r0 + 4]; al[mc][3] = XL[r0 + 8 * S36 + 4];
            }
            #pragma unroll
            for (int nc = 0; nc < 4; nc++) {
                int bi = (32 * nh + 8 * nc + g) * S36 + 8 * ks + t;
                u32 bh0 = WH[bi], bh1 = WH[bi + 4];
                u32 bl0 = WL[bi], bl1 = WL[bi + 4];
                #pragma unroll
                for (int mc = 0; mc < 2; mc++) {
                    mma_bf16(c1[mc][nc], ah[mc], bh0, bh1);
                    mma_bf16(c1[mc][nc], ah[mc], bl0, bl1);
                    mma_bf16(c1[mc][nc], al[mc], bh0, bh1);
                }
            }
        }
        __syncthreads();
        if (c < 15) {
            G1_STS(XHb[1 - par], XLb[1 - par], WHb[1 - par], WLb[1 - par]);
            __syncthreads();
        }
    }

    // write H + bias -> A2 (bf16 split, stride-36 u32 rows)
    #pragma unroll
    for (int mc = 0; mc < 2; mc++) {
        int tok = 32 * tg + 16 * mc + g;
        #pragma unroll
        for (int nc = 0; nc < 4; nc++) {
            int col = 32 * nh + 8 * nc + 2 * t;
            int ci  = 16 * nh + 4 * nc + t;
            float b0v = biasS[col], b1v = biasS[col + 1];
            u32 lo, hi;
            hi = split2(c1[mc][nc][0] + b0v, c1[mc][nc][1] + b1v, lo);
            A2H[tok * S36 + ci] = hi;  A2L[tok * S36 + ci] = lo;
            hi = split2(c1[mc][nc][2] + b0v, c1[mc][nc][3] + b1v, lo);
            A2H[(tok + 8) * S36 + ci] = hi;  A2L[(tok + 8) * S36 + ci] = lo;
        }
    }
    __syncthreads();

    // ===== hoist A-fragments into registers (invariant for all of GEMM2) =====
    u32 AH[2][4][4], AL[2][4][4];
    #pragma unroll
    for (int mc = 0; mc < 2; mc++)
        #pragma unroll
        for (int ks = 0; ks < 4; ks++) {
            int r0 = (32 * tg + 16 * mc + g) * S36 + 8 * ks + t;
            AH[mc][ks][0] = A2H[r0];     AH[mc][ks][1] = A2H[r0 + 8 * S36];
            AH[mc][ks][2] = A2H[r0 + 4]; AH[mc][ks][3] = A2H[r0 + 8 * S36 + 4];
            AL[mc][ks][0] = A2L[r0];     AL[mc][ks][1] = A2L[r0 + 8 * S36];
            AL[mc][ks][2] = A2L[r0 + 4]; AL[mc][ks][3] = A2L[r0 + 8 * S36 + 4];
        }

    // ================= GEMM2: single pass, spill e to global =================
    const uint4* EHg4 = (const uint4*)g_embH;
    const uint4* ELg4 = (const uint4*)g_embL;
    const int rowA0 = 32 * tg + g;        // mc=0 rows: rowA0, rowA0+8
    const int rowA1 = rowA0 + 16;         // mc=1 rows: rowA1, rowA1+8

    // exp + store + rowsum for one tile result
    #define G2_EMIT(nabs_) do { \
        float e00 = __expf(c[0][0]), e01 = __expf(c[0][1]); \
        float e02 = __expf(c[0][2]), e03 = __expf(c[0][3]); \
        float e10 = __expf(c[1][0]), e11 = __expf(c[1][1]); \
        float e12 = __expf(c[1][2]), e13 = __expf(c[1][3]); \
        rs00 += e00 + e01;  rs01 += e02 + e03; \
        rs10 += e10 + e11;  rs11 += e12 + e13; \
        *(float2*)(geb + (size_t)rowA0 * N_TOT + (nabs_)) = make_float2(e00, e01); \
        *(float2*)(geb + (size_t)(rowA0 + 8) * N_TOT + (nabs_)) = make_float2(e02, e03); \
        *(float2*)(geb + (size_t)rowA1 * N_TOT + (nabs_)) = make_float2(e10, e11); \
        *(float2*)(geb + (size_t)(rowA1 + 8) * N_TOT + (nabs_)) = make_float2(e12, e13); \
    } while (0)

    #define RS_FINALIZE(sl_) do { \
        rs00 += __shfl_xor_sync(0xffffffffu, rs00, 1); rs00 += __shfl_xor_sync(0xffffffffu, rs00, 2); \
        rs01 += __shfl_xor_sync(0xffffffffu, rs01, 1); rs01 += __shfl_xor_sync(0xffffffffu, rs01, 2); \
        rs10 += __shfl_xor_sync(0xffffffffu, rs10, 1); rs10 += __shfl_xor_sync(0xffffffffu, rs10, 2); \
        rs11 += __shfl_xor_sync(0xffffffffu, rs11, 1); rs11 += __shfl_xor_sync(0xffffffffu, rs11, 2); \
        if (t == 0) { \
            int tokb = nh * 128 + 32 * tg + g; \
            rsS[tokb] = rs00; rsS[tokb + 8] = rs01; \
            rsS[tokb + 16] = rs10; rsS[tokb + 24] = rs11; \
        } \
        __syncthreads(); \
        if (tid < 128) alphaS[(sl_) * 128 + tid] = impS[tid] / (rsS[tid] + rsS[128 + tid]); \
        __syncthreads(); \
        rs00 = rs01 = rs10 = rs11 = 0.f; \
    } while (0)

    float rs00 = 0.f, rs01 = 0.f, rs10 = 0.f, rs11 = 0.f;
    for (int seg = 0; seg < 4; seg++) {
        __syncthreads();
        int rows = (seg == 3) ? 160 : 256;
        if (tid < rows) {
            const uint4* sH = EHg4 + (size_t)(seg * 256 + tid) * 8;
            const uint4* sL = ELg4 + (size_t)(seg * 256 + tid) * 8;
            uint4* dH = (uint4*)((char*)EH + tid * 144);
            uint4* dL = (uint4*)((char*)EL + tid * 144);
            #pragma unroll
            for (int j = 0; j < 8; j++) { dH[j] = sH[j]; dL[j] = sL[j]; }
        }
        __syncthreads();

        if (seg < 3) {
            for (int i = 0; i < 16; i++) {
                int n0 = nh * 128 + 8 * i;
                float c[2][4] = {{0, 0, 0, 0}, {0, 0, 0, 0}};
                g2_tile_r(AH, AL, EH, EL, g, t, n0, c);
                G2_EMIT(seg * 256 + n0 + 2 * t);
            }
            if (seg >= 1) RS_FINALIZE((seg <= 1) ? 0 : 1);
        } else {
            // REL: local rows 0..127 (slice 2)
            for (int i = 0; i < 8; i++) {
                int n0 = nh * 64 + 8 * i;
                float c[2][4] = {{0, 0, 0, 0}, {0, 0, 0, 0}};
                g2_tile_r(AH, AL, EH, EL, g, t, n0, c);
                G2_EMIT(768 + n0 + 2 * t);
            }
            RS_FINALIZE(2);
            // VAL: local rows 128..159 (slice 3)
            for (int i = 0; i < 2; i++) {
                int n0 = 128 + nh * 16 + 8 * i;
                float c[2][4] = {{0, 0, 0, 0}, {0, 0, 0, 0}};
                g2_tile_r(AH, AL, EH, EL, g, t, n0, c);
                G2_EMIT(768 + n0 + 2 * t);
            }
            RS_FINALIZE(3);
        }
    }

    // ===== w accumulation from spilled e (deterministic, coalesced) =====
    // warps stay within one slice (boundaries are multiples of 32)
    for (int n = tid; n < N_TOT; n += NTHREADS) {
        int sl = (n < N_QK) ? 0 : (n < N_QK + N_V) ? 1 : (n < N_QK + N_V + N_REL) ? 2 : 3;
        const float* al = alphaS + sl * 128;
        const float* ge = geb + n;
        float s = 0.f;
        #pragma unroll 8
        for (int tt = 0; tt < TPB; tt++)
            s += al[tt] * ge[(size_t)tt * N_TOT];
        g_wpart[blockIdx.x][n] = s;
    }

    // ---- completion counter: last block of this batch finalizes ----
    int* lastFlag = (int*)(sm + SM_FLAG);
    __threadfence();
    if (tid == 0) {
        int old = atomicAdd(&g_cnt[bb], 1);
        *lastFlag = (old == 15);
    }
    __syncthreads();
    if (!*lastFlag) return;

    float* sws  = (float*)sm;                 // [928] (aliases A2H, dead now)
    int*   flag = (int*)(sm + 4096);          // [512]
    for (int n = tid; n < N_TOT; n += NTHREADS) {
        float s = 0.0f;
        #pragma unroll
        for (int l = 0; l < 16; l++) s += g_wpart[bb * 16 + l][n];
        sws[n] = s;
    }
    __syncthreads();

    for (int i = tid; i < N_QK; i += NTHREADS) out[OFF_WQK + bb * N_QK + i] = sws[i];
    for (int i = tid; i < N_V;  i += NTHREADS) out[OFF_WV  + bb * N_V  + i] = sws[N_QK + i];

    topk_flags<N_QK, K_QK>(sws, flag, tid);
    __syncthreads();
    for (int i = tid; i < N_QK; i += NTHREADS) {
        if (flag[i]) {
            int pos = 0;
            for (int j = 0; j < i; j++) pos += flag[j];
            out[OFF_IDXQK + bb * K_QK + pos] = (float)i;
        }
    }
    __syncthreads();
    topk_flags<N_V, K_V>(sws + N_QK, flag, tid);
    __syncthreads();
    for (int i = tid; i < N_V; i += NTHREADS) {
        if (flag[i]) {
            int pos = 0;
            for (int j = 0; j < i; j++) pos += flag[j];
            out[OFF_IDXV + bb * K_V + pos] = (float)i;
        }
    }
    __syncthreads();
    topk_flags<N_REL, K_REL>(sws + N_QK + N_V, flag, tid);
    __syncthreads();
    for (int i = tid; i < N_REL; i += NTHREADS) {
        float v = flag[i] ? sws[N_QK + N_V + i] : 0.0f;
        out[OFF_RWQ + bb * N_REL + i] = v;
        out[OFF_RWK + bb * N_REL + i] = v;
    }
    __syncthreads();
    topk_flags<N_VAL, K_VAL>(sws + N_QK + N_V + N_REL, flag, tid);
    __syncthreads();
    for (int i = tid; i < N_VAL; i += NTHREADS)
        out[OFF_VW + bb * N_VAL + i] = flag[i] ? sws[N_QK + N_V + N_REL + i] : 0.0f;
}

extern "C" void kernel_launch(void* const* d_in, const int* in_sizes, int n_in,
                              void* d_out, int out_size) {
    const float* x    = (const float*)d_in[0];
    const float* imp  = (const float*)d_in[1];
    const float* Wm   = (const float*)d_in[2];
    const float* bias = (const float*)d_in[3];
    const float* emb  = (const float*)d_in[4];
    float* out = (float*)d_out;

    cudaFuncSetAttribute(main_kernel, cudaFuncAttributeMaxDynamicSharedMemorySize, SMEM_BYTES);

    prep_emb<<<N_TOT, 64>>>(emb);
    prep_w<<<DSPACE, 256>>>(Wm);
    main_kernel<<<NBLOCKS, NTHREADS, SMEM_BYTES>>>(x, imp, Wm, bias, out);
}

// round 14
// speedup vs baseline: 1.4054x; 1.2474x over previous
#include <cuda_runtime.h>
#include <cuda_bf16.h>
#include <math.h>
#include <string.h>

typedef unsigned long long ull;
typedef unsigned int u32;

// Problem constants
#define BATCH   8
#define SEQ     2048
#define DMODEL  1024
#define DSPACE  64
#define N_QK    512
#define N_V     256
#define N_REL   128
#define N_VAL   32
#define N_TOT   928
#define K_QK    64
#define K_V     32
#define K_REL   16
#define K_VAL   3

#define TPB      128
#define NTHREADS 512
#define NBLOCKS  128               // 16 per batch

// Output layout (float32, reference return order)
#define OFF_IDXQK 0
#define OFF_IDXV  (OFF_IDXQK + BATCH*K_QK)
#define OFF_RWQ   (OFF_IDXV  + BATCH*K_V)
#define OFF_RWK   (OFF_RWQ   + BATCH*N_REL)
#define OFF_VW    (OFF_RWK   + BATCH*N_REL)
#define OFF_WQK   (OFF_VW    + BATCH*N_VAL)
#define OFF_WV    (OFF_WQK   + BATCH*N_QK)

// u32-stride for all MMA smem tiles (32 payload + 4 pad) -> conflict-free frags
#define S36 36

// Shared memory byte offsets
#define SM_A2H   0          // u32[128][36] H hi  (18432)
#define SM_A2L   18432      // u32[128][36] H lo  (18432)
// staging region @36864:
//   GEMM1 buf0: XH 36864(18432) XL 55296(18432) WH 73728(9216) WL 82944(9216)
//   GEMM1 buf1: XH 92160 XL 110592 WH 129024 WL 138240  (end 147456)
//   GEMM2 emb:  EH 36864 (256*36*4=36864)  EL 73728     (end 110592)
//   finalize: sws @0 (aliases A2H), flag @4096
#define SM_EH    36864
#define SM_EL    73728
#define SM_IMP   147456     // float[128]
#define SM_BIAS  147968     // float[64]
#define SM_RS    148224     // float[4][128] = 2048
#define SM_ALPHA 150272     // float[4][128] = 2048
#define SM_FLAG  152320
#define SMEM_BYTES 152576

// device scratch (no allocation allowed)
__device__ u32 g_embH[N_TOT * 32];    // bf16 pairs [n][k2], k2 = d/2
__device__ u32 g_embL[N_TOT * 32];
__device__ u32 g_WH[DSPACE * 512];    // bf16 pairs [n=dspace][k2]
__device__ u32 g_WL[DSPACE * 512];
__device__ float g_e[NBLOCKS][TPB * N_TOT];   // per-block exp scratch (61 MB)
__device__ float g_wpart[NBLOCKS][N_TOT];
__device__ int   g_cnt[BATCH];

// ---------------- helpers ----------------
__device__ __forceinline__ u32 split2(float a, float b, u32& lo) {
    __nv_bfloat162 h = __floats2bfloat162_rn(a, b);
    float ha = __low2float(h), hb = __high2float(h);
    __nv_bfloat162 l = __floats2bfloat162_rn(a - ha, b - hb);
    u32 uh, ul;
    memcpy(&uh, &h, 4);
    memcpy(&ul, &l, 4);
    lo = ul;
    return uh;
}

__device__ __forceinline__ void mma_bf16(float* c, const u32* a, u32 b0, u32 b1) {
    asm volatile(
        "mma.sync.aligned.m16n8k16.row.col.f32.bf16.bf16.f32 "
        "{%0,%1,%2,%3}, {%4,%5,%6,%7}, {%8,%9}, {%0,%1,%2,%3};"
        : "+f"(c[0]), "+f"(c[1]), "+f"(c[2]), "+f"(c[3])
        : "r"(a[0]), "r"(a[1]), "r"(a[2]), "r"(a[3]), "r"(b0), "r"(b1));
}

// ---------------- prep kernels ----------------
__global__ void prep_emb(const float* __restrict__ emb) {
    int r = blockIdx.x;
    int t = threadIdx.x;
    __shared__ float s[64];
    __shared__ float e[64];
    float v = emb[r * DSPACE + t];
    s[t] = v * v;
    __syncthreads();
    #pragma unroll
    for (int o = 32; o > 0; o >>= 1) {
        if (t < o) s[t] += s[t + o];
        __syncthreads();
    }
    e[t] = v / sqrtf(s[0]);
    __syncthreads();
    if (t < 32) {
        u32 lo, hi = split2(e[2 * t], e[2 * t + 1], lo);
        g_embH[r * 32 + t] = hi;
        g_embL[r * 32 + t] = lo;
    }
}

__global__ void prep_w(const float* __restrict__ W) {
    int n = blockIdx.x;
    int tid = threadIdx.x;
    if (n == 0 && tid < BATCH) g_cnt[tid] = 0;
    for (int k2 = tid; k2 < 512; k2 += 256) {
        float a = W[(size_t)(2 * k2) * DSPACE + n];
        float b = W[(size_t)(2 * k2 + 1) * DSPACE + n];
        u32 lo, hi = split2(a, b, lo);
        g_WH[n * 512 + k2] = hi;
        g_WL[n * 512 + k2] = lo;
    }
}

// ---------------- finalize helper ----------------
template<int NN, int KK>
__device__ __forceinline__ void topk_flags(const float* ws, int* flag, int tid) {
    for (int i = tid; i < NN; i += NTHREADS) {
        float wi = ws[i]; int r = 0;
        #pragma unroll 16
        for (int j = 0; j < NN; j++) {
            float wj = ws[j];
            r += (wj > wi) || (wj == wi && j < i);
        }
        flag[i] = (r < KK) ? 1 : 0;
    }
}

// ---------------- GEMM2 tile with register-resident A-fragments ----------------
__device__ __forceinline__ void g2_tile_r(const u32 AH[2][4][4], const u32 AL[2][4][4],
                                          const u32* __restrict__ EH, const u32* __restrict__ EL,
                                          int g, int t, int n0loc, float c[2][4]) {
    #pragma unroll
    for (int ks = 0; ks < 4; ks++) {
        int bi = (n0loc + g) * S36 + 8 * ks + t;
        u32 bh0 = EH[bi], bh1 = EH[bi + 4];
        u32 bl0 = EL[bi], bl1 = EL[bi + 4];
        #pragma unroll
        for (int mc = 0; mc < 2; mc++) {
            mma_bf16(c[mc], AH[mc][ks], bh0, bh1);
            mma_bf16(c[mc], AH[mc][ks], bl0, bl1);
            mma_bf16(c[mc], AL[mc][ks], bh0, bh1);
        }
    }
}

// ---------------- main fused kernel ----------------
__global__ void __launch_bounds__(NTHREADS, 1)
main_kernel(const float* __restrict__ x, const float* __restrict__ imp,
            const float* __restrict__ Wm, const float* __restrict__ bias,
            float* __restrict__ out)
{
    extern __shared__ char sm[];
    u32* A2H = (u32*)(sm + SM_A2H);
    u32* A2L = (u32*)(sm + SM_A2L);
    u32* EH  = (u32*)(sm + SM_EH);
    u32* EL  = (u32*)(sm + SM_EL);
    float* impS   = (float*)(sm + SM_IMP);
    float* biasS  = (float*)(sm + SM_BIAS);
    float* rsS    = (float*)(sm + SM_RS);       // [4][128]
    float* alphaS = (float*)(sm + SM_ALPHA);    // [4][128]

    u32* XHb[2] = {(u32*)(sm + 36864), (u32*)(sm + 92160)};
    u32* XLb[2] = {(u32*)(sm + 55296), (u32*)(sm + 110592)};
    u32* WHb[2] = {(u32*)(sm + 73728), (u32*)(sm + 129024)};
    u32* WLb[2] = {(u32*)(sm + 82944), (u32*)(sm + 138240)};

    const int tid = threadIdx.x;
    const int w = tid >> 5, lane = tid & 31;
    const int g = lane >> 2, t = lane & 3;
    const int tg1 = w >> 1, nh1 = w & 1;     // GEMM1: 8 tok-groups x 2 col-halves
    const int tg2 = w >> 2, nq  = w & 3;     // GEMM2: 4 tok-groups x 4 n-quarters
    const int bb = blockIdx.x >> 4;
    const int s0 = (blockIdx.x & 15) * TPB;
    float* geb = g_e[blockIdx.x];

    if (tid < TPB)    impS[tid]  = imp[bb * SEQ + s0 + tid];
    if (tid < DSPACE) biasS[tid] = bias[tid];

    // ================= GEMM1: H[128,64] = X[128,1024] @ W + b =================
    float c1[4][4];
    #pragma unroll
    for (int nc = 0; nc < 4; nc++)
        #pragma unroll
        for (int j = 0; j < 4; j++) c1[nc][j] = 0.f;

    const float4* Xg4 = (const float4*)(x + (size_t)(bb * SEQ + s0) * DMODEL);
    const uint4* WHg4 = (const uint4*)g_WH;
    const uint4* WLg4 = (const uint4*)g_WL;
    const int tokS1 = tid >> 2, hS1 = tid & 3;   // X staging: 128 tok x 4 quarters
    const int nS1   = tid >> 3, qS1 = tid & 7;   // W staging: 64 n x 8 chunks

    float4 xr[4];
    uint4 wha, wla;

    #define G1_LDG(cc) do { \
        _Pragma("unroll") \
        for (int i = 0; i < 4; i++) xr[i] = Xg4[(size_t)tokS1 * 256 + (cc) * 16 + hS1 * 4 + i]; \
        int ws_ = nS1 * 128 + (cc) * 8 + qS1; \
        wha = WHg4[ws_]; wla = WLg4[ws_]; \
    } while (0)

    #define G1_STS(XH_, XL_, WH_, WL_) do { \
        _Pragma("unroll") \
        for (int i = 0; i < 4; i++) { \
            u32 l0, l1; \
            u32 h0 = split2(xr[i].x, xr[i].y, l0); \
            u32 h1 = split2(xr[i].z, xr[i].w, l1); \
            int di = tokS1 * S36 + hS1 * 8 + 2 * i; \
            *(ull*)((XH_) + di) = ((ull)h1 << 32) | h0; \
            *(ull*)((XL_) + di) = ((ull)l1 << 32) | l0; \
        } \
        int wd = nS1 * S36 + qS1 * 4; \
        *(uint4*)((WH_) + wd) = wha; \
        *(uint4*)((WL_) + wd) = wla; \
    } while (0)

    G1_LDG(0);
    G1_STS(XHb[0], XLb[0], WHb[0], WLb[0]);
    __syncthreads();

    for (int c = 0; c < 16; c++) {
        const int par = c & 1;
        if (c < 15) G1_LDG(c + 1);
        const u32* XH = XHb[par]; const u32* XL = XLb[par];
        const u32* WH = WHb[par]; const u32* WL = WLb[par];
        #pragma unroll
        for (int ks = 0; ks < 4; ks++) {
            int r0 = (16 * tg1 + g) * S36 + 8 * ks + t;
            u32 ah[4] = {XH[r0], XH[r0 + 8 * S36], XH[r0 + 4], XH[r0 + 8 * S36 + 4]};
            u32 al[4] = {XL[r0], XL[r0 + 8 * S36], XL[r0 + 4], XL[r0 + 8 * S36 + 4]};
            #pragma unroll
            for (int nc = 0; nc < 4; nc++) {
                int bi = (32 * nh1 + 8 * nc + g) * S36 + 8 * ks + t;
                u32 bh0 = WH[bi], bh1 = WH[bi + 4];
                u32 bl0 = WL[bi], bl1 = WL[bi + 4];
                mma_bf16(c1[nc], ah, bh0, bh1);
                mma_bf16(c1[nc], ah, bl0, bl1);
                mma_bf16(c1[nc], al, bh0, bh1);
            }
        }
        __syncthreads();
        if (c < 15) {
            G1_STS(XHb[1 - par], XLb[1 - par], WHb[1 - par], WLb[1 - par]);
            __syncthreads();
        }
    }

    // write H + bias -> A2 (bf16 split, stride-36 u32 rows)
    {
        int tok = 16 * tg1 + g;
        #pragma unroll
        for (int nc = 0; nc < 4; nc++) {
            int col = 32 * nh1 + 8 * nc + 2 * t;
            int ci  = 16 * nh1 + 4 * nc + t;
            float b0v = biasS[col], b1v = biasS[col + 1];
            u32 lo, hi;
            hi = split2(c1[nc][0] + b0v, c1[nc][1] + b1v, lo);
            A2H[tok * S36 + ci] = hi;  A2L[tok * S36 + ci] = lo;
            hi = split2(c1[nc][2] + b0v, c1[nc][3] + b1v, lo);
            A2H[(tok + 8) * S36 + ci] = hi;  A2L[(tok + 8) * S36 + ci] = lo;
        }
    }
    __syncthreads();

    // ===== hoist A-fragments into registers (invariant for all of GEMM2) =====
    u32 AH[2][4][4], AL[2][4][4];
    #pragma unroll
    for (int mc = 0; mc < 2; mc++)
        #pragma unroll
        for (int ks = 0; ks < 4; ks++) {
            int r0 = (32 * tg2 + 16 * mc + g) * S36 + 8 * ks + t;
            AH[mc][ks][0] = A2H[r0];     AH[mc][ks][1] = A2H[r0 + 8 * S36];
            AH[mc][ks][2] = A2H[r0 + 4]; AH[mc][ks][3] = A2H[r0 + 8 * S36 + 4];
            AL[mc][ks][0] = A2L[r0];     AL[mc][ks][1] = A2L[r0 + 8 * S36];
            AL[mc][ks][2] = A2L[r0 + 4]; AL[mc][ks][3] = A2L[r0 + 8 * S36 + 4];
        }

    // ================= GEMM2: single pass, spill e to global =================
    const uint4* EHg4 = (const uint4*)g_embH;
    const uint4* ELg4 = (const uint4*)g_embL;
    const int rowA0 = 32 * tg2 + g;       // mc=0 rows: rowA0, rowA0+8
    const int rowA1 = rowA0 + 16;         // mc=1 rows: rowA1, rowA1+8
    const int rowE  = tid >> 1, halfE = tid & 1;

    #define G2_EMIT(nabs_) do { \
        float e00 = __expf(c[0][0]), e01 = __expf(c[0][1]); \
        float e02 = __expf(c[0][2]), e03 = __expf(c[0][3]); \
        float e10 = __expf(c[1][0]), e11 = __expf(c[1][1]); \
        float e12 = __expf(c[1][2]), e13 = __expf(c[1][3]); \
        rs00 += e00 + e01;  rs01 += e02 + e03; \
        rs10 += e10 + e11;  rs11 += e12 + e13; \
        *(float2*)(geb + (size_t)rowA0 * N_TOT + (nabs_)) = make_float2(e00, e01); \
        *(float2*)(geb + (size_t)(rowA0 + 8) * N_TOT + (nabs_)) = make_float2(e02, e03); \
        *(float2*)(geb + (size_t)rowA1 * N_TOT + (nabs_)) = make_float2(e10, e11); \
        *(float2*)(geb + (size_t)(rowA1 + 8) * N_TOT + (nabs_)) = make_float2(e12, e13); \
    } while (0)

    #define RS_FINALIZE(sl_) do { \
        rs00 += __shfl_xor_sync(0xffffffffu, rs00, 1); rs00 += __shfl_xor_sync(0xffffffffu, rs00, 2); \
        rs01 += __shfl_xor_sync(0xffffffffu, rs01, 1); rs01 += __shfl_xor_sync(0xffffffffu, rs01, 2); \
        rs10 += __shfl_xor_sync(0xffffffffu, rs10, 1); rs10 += __shfl_xor_sync(0xffffffffu, rs10, 2); \
        rs11 += __shfl_xor_sync(0xffffffffu, rs11, 1); rs11 += __shfl_xor_sync(0xffffffffu, rs11, 2); \
        if (t == 0) { \
            int tokb = 32 * tg2 + g; \
            rsS[nq * 128 + tokb]      = rs00; \
            rsS[nq * 128 + tokb + 8]  = rs01; \
            rsS[nq * 128 + tokb + 16] = rs10; \
            rsS[nq * 128 + tokb + 24] = rs11; \
        } \
        __syncthreads(); \
        if (tid < 128) \
            alphaS[(sl_) * 128 + tid] = impS[tid] / \
                (rsS[tid] + rsS[128 + tid] + rsS[256 + tid] + rsS[384 + tid]); \
        __syncthreads(); \
        rs00 = rs01 = rs10 = rs11 = 0.f; \
    } while (0)

    float rs00 = 0.f, rs01 = 0.f, rs10 = 0.f, rs11 = 0.f;
    for (int seg = 0; seg < 4; seg++) {
        __syncthreads();
        int rows = (seg == 3) ? 160 : 256;
        if (rowE < rows) {
            const uint4* sH = EHg4 + (size_t)(seg * 256 + rowE) * 8 + halfE * 4;
            const uint4* sL = ELg4 + (size_t)(seg * 256 + rowE) * 8 + halfE * 4;
            uint4* dH = (uint4*)((char*)EH + rowE * 144 + halfE * 64);
            uint4* dL = (uint4*)((char*)EL + rowE * 144 + halfE * 64);
            #pragma unroll
            for (int j = 0; j < 4; j++) { dH[j] = sH[j]; dL[j] = sL[j]; }
        }
        __syncthreads();

        if (seg < 3) {
            for (int i = 0; i < 8; i++) {
                int n0 = nq * 64 + 8 * i;
                float c[2][4] = {{0, 0, 0, 0}, {0, 0, 0, 0}};
                g2_tile_r(AH, AL, EH, EL, g, t, n0, c);
                G2_EMIT(seg * 256 + n0 + 2 * t);
            }
            if (seg >= 1) RS_FINALIZE((seg <= 1) ? 0 : 1);
        } else {
            // REL: local rows 0..127 (slice 2)
            for (int i = 0; i < 4; i++) {
                int n0 = nq * 32 + 8 * i;
                float c[2][4] = {{0, 0, 0, 0}, {0, 0, 0, 0}};
                g2_tile_r(AH, AL, EH, EL, g, t, n0, c);
                G2_EMIT(768 + n0 + 2 * t);
            }
            RS_FINALIZE(2);
            // VAL: local rows 128..159 (slice 3)
            {
                int n0 = 128 + nq * 8;
                float c[2][4] = {{0, 0, 0, 0}, {0, 0, 0, 0}};
                g2_tile_r(AH, AL, EH, EL, g, t, n0, c);
                G2_EMIT(768 + n0 + 2 * t);
            }
            RS_FINALIZE(3);
        }
    }

    // ===== w accumulation from spilled e (deterministic, coalesced) =====
    for (int n = tid; n < N_TOT; n += NTHREADS) {
        int sl = (n < N_QK) ? 0 : (n < N_QK + N_V) ? 1 : (n < N_QK + N_V + N_REL) ? 2 : 3;
        const float* al = alphaS + sl * 128;
        const float* ge = geb + n;
        float s = 0.f;
        #pragma unroll 8
        for (int tt = 0; tt < TPB; tt++)
            s += al[tt] * ge[(size_t)tt * N_TOT];
        g_wpart[blockIdx.x][n] = s;
    }

    // ---- completion counter: last block of this batch finalizes ----
    int* lastFlag = (int*)(sm + SM_FLAG);
    __threadfence();
    if (tid == 0) {
        int old = atomicAdd(&g_cnt[bb], 1);
        *lastFlag = (old == 15);
    }
    __syncthreads();
    if (!*lastFlag) return;

    float* sws  = (float*)sm;                 // [928] (aliases A2H, dead now)
    int*   flag = (int*)(sm + 4096);          // [512]
    for (int n = tid; n < N_TOT; n += NTHREADS) {
        float s = 0.0f;
        #pragma unroll
        for (int l = 0; l < 16; l++) s += g_wpart[bb * 16 + l][n];
        sws[n] = s;
    }
    __syncthreads();

    for (int i = tid; i < N_QK; i += NTHREADS) out[OFF_WQK + bb * N_QK + i] = sws[i];
    for (int i = tid; i < N_V;  i += NTHREADS) out[OFF_WV  + bb * N_V  + i] = sws[N_QK + i];

    topk_flags<N_QK, K_QK>(sws, flag, tid);
    __syncthreads();
    for (int i = tid; i < N_QK; i += NTHREADS) {
        if (flag[i]) {
            int pos = 0;
            for (int j = 0; j < i; j++) pos += flag[j];
            out[OFF_IDXQK + bb * K_QK + pos] = (float)i;
        }
    }
    __syncthreads();
    topk_flags<N_V, K_V>(sws + N_QK, flag, tid);
    __syncthreads();
    for (int i = tid; i < N_V; i += NTHREADS) {
        if (flag[i]) {
            int pos = 0;
            for (int j = 0; j < i; j++) pos += flag[j];
            out[OFF_IDXV + bb * K_V + pos] = (float)i;
        }
    }
    __syncthreads();
    topk_flags<N_REL, K_REL>(sws + N_QK + N_V, flag, tid);
    __syncthreads();
    for (int i = tid; i < N_REL; i += NTHREADS) {
        float v = flag[i] ? sws[N_QK + N_V + i] : 0.0f;
        out[OFF_RWQ + bb * N_REL + i] = v;
        out[OFF_RWK + bb * N_REL + i] = v;
    }
    __syncthreads();
    topk_flags<N_VAL, K_VAL>(sws + N_QK + N_V + N_REL, flag, tid);
    __syncthreads();
    for (int i = tid; i < N_VAL; i += NTHREADS)
        out[OFF_VW + bb * N_VAL + i] = flag[i] ? sws[N_QK + N_V + N_REL + i] : 0.0f;
}

extern "C" void kernel_launch(void* const* d_in, const int* in_sizes, int n_in,
                              void* d_out, int out_size) {
    const float* x    = (const float*)d_in[0];
    const float* imp  = (const float*)d_in[1];
    const float* Wm   = (const float*)d_in[2];
    const float* bias = (const float*)d_in[3];
    const float* emb  = (const float*)d_in[4];
    float* out = (float*)d_out;

    cudaFuncSetAttribute(main_kernel, cudaFuncAttributeMaxDynamicSharedMemorySize, SMEM_BYTES);

    prep_emb<<<N_TOT, 64>>>(emb);
    prep_w<<<DSPACE, 256>>>(Wm);
    main_kernel<<<NBLOCKS, NTHREADS, SMEM_BYTES>>>(x, imp, Wm, bias, out);
}